// round 9
// baseline (speedup 1.0000x reference)
#include <cuda_runtime.h>
#include <cuda_fp16.h>
#include <cstddef>

// Problem dims (compile-time)
#define Bz 512
#define Tz 128
#define Iz 512
#define Hz 512
#define Cz 97
#define Sz 26
#define XI (Iz + Cz)   // 609

// ---------------------------------------------------------------------------
// K-dimension permutation (applied to ALL K-side fp16 arrays so GEMM fragment
// loads become LDS.64).  Within each 16-half group, stored half2-unit s holds
// logical unit perm[s] = {0,4,1,5,2,6,3,7}[s].
// ---------------------------------------------------------------------------
__device__ __forceinline__ int kperm_src(int kp) {   // stored k' -> logical k
    int s = (kp >> 1) & 7;
    int u = (s >> 1) | ((s & 1) << 2);
    return (kp & ~15) | (u << 1) | (kp & 1);
}
__device__ __forceinline__ int kperm_dst(int k) {    // logical k -> stored k'
    int u = (k >> 1) & 7;
    int s = ((u & 3) << 1) | (u >> 2);
    return (k & ~15) | (s << 1) | (k & 1);
}

// ---------------------------------------------------------------------------
// Scratch (device globals; no runtime allocation allowed)
// ---------------------------------------------------------------------------
__device__ alignas(16) __half g_feat16[(size_t)Bz * Tz * Hz];  // [B,T,H] (h logical)
__device__ alignas(16) __half g_bh16[(size_t)Bz * Tz * Iz];    // batch_H fp16, K-permuted
__device__ alignas(16) __half g_h16[Bz * Hz];                  // hidden fp16, K-permuted
__device__ alignas(16) float  g_c[Bz * Hz];                    // cell fp32 (logical j)
__device__ alignas(16) float  g_hp[Bz * Hz];                   // hidden proj fp32 (logical h)
__device__ alignas(16) __half g_ctx16[Bz * Iz];                // context fp16, K-permuted
__device__ alignas(16) float  g_gates[Bz * 2048];              // h-part of gates (n'=4j+g)
__device__ alignas(16) __half g_outh16[(size_t)Bz * Sz * Hz];  // [B,S,H] K-permuted
__device__ alignas(16) __half g_Wcat16[2560 * 512];            // [perm(W_hh); W_hid], K-perm
__device__ alignas(16) float  g_bcat[2560];
__device__ alignas(16) __half g_Wih16[2048 * 512];             // perm rows, K-perm cols
__device__ alignas(16) __half g_Wfeat16[512 * 512];            // K-perm cols
__device__ alignas(16) __half g_Wgen16[128 * 512];             // padded, K-perm cols

// ---------------------------------------------------------------------------
__global__ void init_kernel() {
    int i = blockIdx.x * blockDim.x + threadIdx.x;
    if (i < Bz * Hz) { g_h16[i] = __float2half(0.f); g_c[i] = 0.f; }
}

// one-time: batch_H fp32 -> fp16, K-permuted.  One 16-half group per thread.
__global__ void conv_bh_kernel(const float* __restrict__ bh) {
    size_t gidx = (size_t)blockIdx.x * blockDim.x + threadIdx.x;
    size_t ngroups = (size_t)Bz * Tz * Iz / 16;
    if (gidx >= ngroups) return;
    const float4* src = (const float4*)(bh + gidx * 16);
    float4 f0 = src[0], f1 = src[1], f2 = src[2], f3 = src[3];
    float f[16] = {f0.x, f0.y, f0.z, f0.w, f1.x, f1.y, f1.z, f1.w,
                   f2.x, f2.y, f2.z, f2.w, f3.x, f3.y, f3.z, f3.w};
    const int perm[8] = {0, 4, 1, 5, 2, 6, 3, 7};
    __half2 o[8];
#pragma unroll
    for (int s = 0; s < 8; s++)
        o[s] = __floats2half2_rn(f[2 * perm[s]], f[2 * perm[s] + 1]);
    uint4* dst = (uint4*)(g_bh16 + gidx * 16);
    dst[0] = *(uint4*)&o[0];
    dst[1] = *(uint4*)&o[4];
}

// gate-row permutation: n' in [0,2048) -> original row = (n'&3)*512 + (n'>>2)
__device__ __forceinline__ int orig_row(int np) { return (np & 3) * 512 + (np >> 2); }

__global__ void prep_wcat_kernel(const float* __restrict__ W_hh,
                                 const float* __restrict__ W_hid,
                                 const float* __restrict__ b_ih,
                                 const float* __restrict__ b_hh,
                                 const float* __restrict__ b_hid) {
    int idx = blockIdx.x * blockDim.x + threadIdx.x;
    if (idx < 2560 * 512) {
        int n = idx >> 9, kp = idx & 511;
        int k = kperm_src(kp);
        float v = (n < 2048) ? W_hh[(size_t)orig_row(n) * 512 + k]
                             : W_hid[(size_t)(n - 2048) * 512 + k];
        g_Wcat16[idx] = __float2half(v);
    }
    if (idx < 2560)
        g_bcat[idx] = (idx < 2048) ? (b_ih[orig_row(idx)] + b_hh[orig_row(idx)])
                                   : b_hid[idx - 2048];
}

__global__ void prep_wih_kernel(const float* __restrict__ W_ih) {
    int idx = blockIdx.x * blockDim.x + threadIdx.x;
    if (idx < 2048 * 512) {
        int n = idx >> 9, kp = idx & 511;
        g_Wih16[idx] = __float2half(W_ih[(size_t)orig_row(n) * XI + kperm_src(kp)]);
    }
}

__global__ void prep_wfeat_kernel(const float* __restrict__ W_feat) {
    int idx = blockIdx.x * blockDim.x + threadIdx.x;
    if (idx < 512 * 512) {
        int n = idx >> 9, kp = idx & 511;
        g_Wfeat16[idx] = __float2half(W_feat[(size_t)n * 512 + kperm_src(kp)]);
    }
}

__global__ void prep_wgen_kernel(const float* __restrict__ W_gen) {
    int idx = blockIdx.x * blockDim.x + threadIdx.x;
    if (idx < 128 * 512) {
        int n = idx >> 9, kp = idx & 511;
        g_Wgen16[idx] = __float2half((n < Cz) ? W_gen[(size_t)n * 512 + kperm_src(kp)] : 0.f);
    }
}

// ---------------------------------------------------------------------------
// fp16 tensor-core GEMM:  C[m,n] = sum_k A[m,k]*B[n,k]  (K=512, K-permuted)
// Tile 128x64, BK=32 halves, 8 warps (4m x 2n), warp 32x32 via m16n8k16.
// Fragment loads are LDS.64 thanks to the K-permutation.
// ---------------------------------------------------------------------------
__device__ __forceinline__ void mma16(float* c, const unsigned* a, const unsigned* b) {
    asm volatile(
        "mma.sync.aligned.m16n8k16.row.col.f32.f16.f16.f32 "
        "{%0,%1,%2,%3}, {%4,%5,%6,%7}, {%8,%9}, {%0,%1,%2,%3};"
        : "+f"(c[0]), "+f"(c[1]), "+f"(c[2]), "+f"(c[3])
        : "r"(a[0]), "r"(a[1]), "r"(a[2]), "r"(a[3]), "r"(b[0]), "r"(b[1]));
}

__device__ __forceinline__ float sigmoidf_(float x) {
    return 1.f / (1.f + __expf(-x));
}

template <int MODE>
__global__ __launch_bounds__(256) void h16gemm(
    const __half* __restrict__ A, const __half* __restrict__ B,
    const float* __restrict__ Wih_full, const int* __restrict__ text,
    const float* __restrict__ bias, float* __restrict__ Cout, int step)
{
    __shared__ alignas(16) unsigned As2[128][20];
    __shared__ alignas(16) unsigned Bs2[64][20];

    const int tid  = threadIdx.x;
    const int warp = tid >> 5, lane = tid & 31;
    const int wm = warp & 3, wn = warp >> 2;
    const int g  = lane >> 2, tg = lane & 3;
    const int m0 = blockIdx.y * 128, n0 = blockIdx.x * 64;

    const int ar0 = tid >> 2, aq = tid & 3;
    const __half* Ap0 = A + (size_t)(m0 + ar0) * 512 + aq * 8;
    const __half* Ap1 = A + (size_t)(m0 + ar0 + 64) * 512 + aq * 8;
    const __half* Bp  = B + (size_t)(n0 + (tid >> 2)) * 512 + (tid & 3) * 8;

    float acc[2][4][4] = {};
    uint4 ra0 = *(const uint4*)Ap0;
    uint4 ra1 = *(const uint4*)Ap1;
    uint4 rb  = *(const uint4*)Bp;

    for (int kt = 0; kt < 16; kt++) {
        *(uint4*)&As2[ar0][aq * 4]      = ra0;
        *(uint4*)&As2[ar0 + 64][aq * 4] = ra1;
        *(uint4*)&Bs2[tid >> 2][(tid & 3) * 4] = rb;
        __syncthreads();

        if (kt < 15) {
            ra0 = *(const uint4*)(Ap0 + (kt + 1) * 32);
            ra1 = *(const uint4*)(Ap1 + (kt + 1) * 32);
            rb  = *(const uint4*)(Bp + (kt + 1) * 32);
        }

#pragma unroll
        for (int ks = 0; ks < 2; ks++) {
            const int kb = ks * 8;
            unsigned af[2][4], bf[4][2];
#pragma unroll
            for (int mi = 0; mi < 2; mi++) {
                int mr = wm * 32 + mi * 16 + g;
                uint2 lo = *(const uint2*)&As2[mr][kb + 2 * tg];
                uint2 hi = *(const uint2*)&As2[mr + 8][kb + 2 * tg];
                af[mi][0] = lo.x; af[mi][1] = hi.x;
                af[mi][2] = lo.y; af[mi][3] = hi.y;
            }
#pragma unroll
            for (int ni = 0; ni < 4; ni++) {
                int nr = wn * 32 + ni * 8 + g;
                uint2 bb = *(const uint2*)&Bs2[nr][kb + 2 * tg];
                bf[ni][0] = bb.x; bf[ni][1] = bb.y;
            }
#pragma unroll
            for (int mi = 0; mi < 2; mi++)
#pragma unroll
                for (int ni = 0; ni < 4; ni++)
                    mma16(acc[mi][ni], af[mi], bf[ni]);
        }
        __syncthreads();
    }

    // epilogue
#pragma unroll
    for (int mi = 0; mi < 2; mi++) {
#pragma unroll
        for (int ni = 0; ni < 4; ni++) {
            const int m = m0 + wm * 32 + mi * 16 + g;
            const int n = n0 + wn * 32 + ni * 8 + 2 * tg;
            const float* c = acc[mi][ni];

            if (MODE == 0) {
                *(__half2*)&g_feat16[(size_t)m * 512 + n] =
                    __floats2half2_rn(c[0], c[1]);
                *(__half2*)&g_feat16[(size_t)(m + 8) * 512 + n] =
                    __floats2half2_rn(c[2], c[3]);
            } else if (MODE == 1) {
                if (n < 2048) {
                    g_gates[(size_t)m * 2048 + n]           = c[0] + g_bcat[n];
                    g_gates[(size_t)m * 2048 + n + 1]       = c[1] + g_bcat[n + 1];
                    g_gates[(size_t)(m + 8) * 2048 + n]     = c[2] + g_bcat[n];
                    g_gates[(size_t)(m + 8) * 2048 + n + 1] = c[3] + g_bcat[n + 1];
                } else {
                    int nn = n - 2048;
                    g_hp[(size_t)m * 512 + nn]           = c[0] + g_bcat[n];
                    g_hp[(size_t)m * 512 + nn + 1]       = c[1] + g_bcat[n + 1];
                    g_hp[(size_t)(m + 8) * 512 + nn]     = c[2] + g_bcat[n];
                    g_hp[(size_t)(m + 8) * 512 + nn + 1] = c[3] + g_bcat[n + 1];
                }
            } else if (MODE == 2) {
                // full gate pre-activations (permuted gate layout n' = 4j + gate)
                const int cls0 = text[m * Sz + step];
                const int cls1 = text[(m + 8) * Sz + step];
                float v0 = c[0] + g_gates[(size_t)m * 2048 + n]
                         + Wih_full[(size_t)orig_row(n) * XI + Iz + cls0];
                float v1 = c[1] + g_gates[(size_t)m * 2048 + n + 1]
                         + Wih_full[(size_t)orig_row(n + 1) * XI + Iz + cls0];
                float v2 = c[2] + g_gates[(size_t)(m + 8) * 2048 + n]
                         + Wih_full[(size_t)orig_row(n) * XI + Iz + cls1];
                float v3 = c[3] + g_gates[(size_t)(m + 8) * 2048 + n + 1]
                         + Wih_full[(size_t)orig_row(n + 1) * XI + Iz + cls1];

                // lane-pair exchange: tg even holds (i,f), tg odd holds (g,o)
                float o0 = __shfl_xor_sync(0xffffffffu, v0, 1);
                float o1 = __shfl_xor_sync(0xffffffffu, v1, 1);
                float o2 = __shfl_xor_sync(0xffffffffu, v2, 1);
                float o3 = __shfl_xor_sync(0xffffffffu, v3, 1);

                const int j = n >> 2;
                int row; float i_, f_, g_, q_;
                if ((tg & 1) == 0) { row = m;     i_ = v0; f_ = v1; g_ = o0; q_ = o1; }
                else              { row = m + 8; i_ = o2; f_ = o3; g_ = v2; q_ = v3; }
                float cp = g_c[row * 512 + j];
                float ig = sigmoidf_(i_);
                float fg = sigmoidf_(f_);
                float gg = tanhf(g_);
                float og = sigmoidf_(q_);
                float cn = fg * cp + ig * gg;
                float hn = og * tanhf(cn);
                g_c[row * 512 + j] = cn;
                __half hh = __float2half(hn);
                int jp = kperm_dst(j);              // K-permuted storage position
                g_h16[row * 512 + jp] = hh;
                g_outh16[((size_t)row * Sz + step) * 512 + jp] = hh;
            } else {  // MODE 3: generator
                if (n < Cz) {
                    Cout[(size_t)m * Cz + n]       = c[0] + bias[n];
                    Cout[(size_t)(m + 8) * Cz + n] = c[2] + bias[n];
                }
                if (n + 1 < Cz) {
                    Cout[(size_t)m * Cz + n + 1]       = c[1] + bias[n + 1];
                    Cout[(size_t)(m + 8) * Cz + n + 1] = c[3] + bias[n + 1];
                }
            }
        }
    }
}

// ---------------------------------------------------------------------------
// Attention: one block per batch b.  feat16 columns are logical (unpermuted);
// bh16 columns are K-permuted, so ctx comes out K-permuted automatically.
// ---------------------------------------------------------------------------
__global__ __launch_bounds__(256) void attn_kernel(const float* __restrict__ w_score)
{
    __shared__ float hp_s[Hz];
    __shared__ float ws_s[Hz];
    __shared__ float e_s[Tz];
    __shared__ float red[8];
    __shared__ float cred[4][64][9];

    const int b = blockIdx.x;
    const int tid = threadIdx.x;
    const int warp = tid >> 5, lane = tid & 31;

    for (int i = tid; i < Hz; i += 256) {
        hp_s[i] = g_hp[(size_t)b * Hz + i];
        ws_s[i] = w_score[i];
    }
    __syncthreads();

    // scores: e[t] = sum_h tanh(feat16[b,t,h] + hp[h]) * ws[h]
    for (int t = warp; t < Tz; t += 8) {
        const uint4* fr = (const uint4*)(g_feat16 + ((size_t)b * Tz + t) * Hz);
        float s = 0.f;
#pragma unroll
        for (int rep = 0; rep < 2; rep++) {
            uint4 v = fr[rep * 32 + lane];
            const int h0 = rep * 256 + lane * 8;
            const __half2* hv = (const __half2*)&v;
#pragma unroll
            for (int j = 0; j < 4; j++) {
                float2 f = __half22float2(hv[j]);
                float x0 = f.x + hp_s[h0 + 2 * j];
                float x1 = f.y + hp_s[h0 + 2 * j + 1];
                float t0, t1;
                asm("tanh.approx.f32 %0, %1;" : "=f"(t0) : "f"(x0));
                asm("tanh.approx.f32 %0, %1;" : "=f"(t1) : "f"(x1));
                s = fmaf(t0, ws_s[h0 + 2 * j], s);
                s = fmaf(t1, ws_s[h0 + 2 * j + 1], s);
            }
        }
#pragma unroll
        for (int o = 16; o; o >>= 1) s += __shfl_xor_sync(0xffffffffu, s, o);
        if (lane == 0) e_s[t] = s;
    }
    __syncthreads();

    // softmax over T=128
    float v = (tid < Tz) ? e_s[tid] : -1e30f;
    float mval = v;
#pragma unroll
    for (int o = 16; o; o >>= 1) mval = fmaxf(mval, __shfl_xor_sync(0xffffffffu, mval, o));
    if (lane == 0) red[warp] = mval;
    __syncthreads();
    float mx = red[0];
#pragma unroll
    for (int w = 1; w < 8; w++) mx = fmaxf(mx, red[w]);
    float ex = (tid < Tz) ? __expf(v - mx) : 0.f;
    float ssum = ex;
#pragma unroll
    for (int o = 16; o; o >>= 1) ssum += __shfl_xor_sync(0xffffffffu, ssum, o);
    __syncthreads();
    if (lane == 0) red[warp] = ssum;
    __syncthreads();
    float tot = red[0] + red[1] + red[2] + red[3] + red[4] + red[5] + red[6] + red[7];
    if (tid < Tz) e_s[tid] = ex / tot;
    __syncthreads();

    // ctx[i] = sum_t alpha[t] * bh16[b,t,i]
    // uint4 loads (8 cols/thread), 4-way t-parallel, smem reduction.
    const uint4* bh4 = (const uint4*)(g_bh16 + (size_t)b * Tz * Iz);
    const int tq = tid >> 6;     // t-offset group 0..3
    const int tc = tid & 63;     // column chunk (8 halves)
    float a8[8] = {};
#pragma unroll 8
    for (int t = tq; t < Tz; t += 4) {
        uint4 vv = bh4[(size_t)t * 64 + tc];
        float al = e_s[t];
        const __half2* hv = (const __half2*)&vv;
#pragma unroll
        for (int j = 0; j < 4; j++) {
            float2 f = __half22float2(hv[j]);
            a8[2 * j]     = fmaf(al, f.x, a8[2 * j]);
            a8[2 * j + 1] = fmaf(al, f.y, a8[2 * j + 1]);
        }
    }
    if (tq != 0) {
#pragma unroll
        for (int j = 0; j < 8; j++) cred[tq][tc][j] = a8[j];
    }
    __syncthreads();
    if (tq == 0) {
        __half2 o[4];
#pragma unroll
        for (int j = 0; j < 4; j++) {
            float rx = a8[2 * j]     + cred[1][tc][2 * j]     + cred[2][tc][2 * j]     + cred[3][tc][2 * j];
            float ry = a8[2 * j + 1] + cred[1][tc][2 * j + 1] + cred[2][tc][2 * j + 1] + cred[3][tc][2 * j + 1];
            o[j] = __floats2half2_rn(rx, ry);
        }
        *(uint4*)&g_ctx16[(size_t)b * Iz + tc * 8] = *(uint4*)&o[0];
    }
}

// ---------------------------------------------------------------------------
// launch
// ---------------------------------------------------------------------------
extern "C" void kernel_launch(void* const* d_in, const int* in_sizes, int n_in,
                              void* d_out, int out_size) {
    const float* batch_H = (const float*)d_in[0];
    const int*   text    = (const int*)d_in[1];
    const float* W_feat  = (const float*)d_in[2];
    const float* W_hid   = (const float*)d_in[3];
    const float* b_hid   = (const float*)d_in[4];
    const float* w_score = (const float*)d_in[5];
    const float* W_ih    = (const float*)d_in[6];
    const float* W_hh    = (const float*)d_in[7];
    const float* b_ih    = (const float*)d_in[8];
    const float* b_hh    = (const float*)d_in[9];
    const float* W_gen   = (const float*)d_in[10];
    const float* b_gen   = (const float*)d_in[11];
    float* out = (float*)d_out;

    __half *p_bh16, *p_h16, *p_ctx16, *p_outh16, *p_wcat16, *p_wih16, *p_wfeat16, *p_wgen16;
    cudaGetSymbolAddress((void**)&p_bh16,    g_bh16);
    cudaGetSymbolAddress((void**)&p_h16,     g_h16);
    cudaGetSymbolAddress((void**)&p_ctx16,   g_ctx16);
    cudaGetSymbolAddress((void**)&p_outh16,  g_outh16);
    cudaGetSymbolAddress((void**)&p_wcat16,  g_Wcat16);
    cudaGetSymbolAddress((void**)&p_wih16,   g_Wih16);
    cudaGetSymbolAddress((void**)&p_wfeat16, g_Wfeat16);
    cudaGetSymbolAddress((void**)&p_wgen16,  g_Wgen16);

    // one-time prep
    init_kernel<<<(Bz * Hz + 255) / 256, 256>>>();
    {
        size_t ngroups = (size_t)Bz * Tz * Iz / 16;
        conv_bh_kernel<<<(int)((ngroups + 255) / 256), 256>>>(batch_H);
    }
    prep_wcat_kernel<<<(2560 * 512 + 255) / 256, 256>>>(W_hh, W_hid, b_ih, b_hh, b_hid);
    prep_wih_kernel<<<(2048 * 512 + 255) / 256, 256>>>(W_ih);
    prep_wfeat_kernel<<<(512 * 512 + 255) / 256, 256>>>(W_feat);
    prep_wgen_kernel<<<(128 * 512 + 255) / 256, 256>>>(W_gen);

    // feat16 = fp16(batch_H @ W_feat^T) : [B*T, H]
    h16gemm<0><<<dim3(Hz / 64, (Bz * Tz) / 128), 256>>>(
        p_bh16, p_wfeat16, nullptr, nullptr, nullptr, nullptr, 0);

    for (int s = 0; s < Sz; s++) {
        // gates_h (permuted) = h@perm(W_hh)^T + biases ; hp = h@W_hid^T + b_hid
        h16gemm<1><<<dim3(2560 / 64, Bz / 128), 256>>>(
            p_h16, p_wcat16, nullptr, nullptr, nullptr, nullptr, 0);

        // attention + context (fp16 ctx, K-permuted)
        attn_kernel<<<Bz, 256>>>(w_score);

        // gates += ctx@perm(W_ih)^T + one-hot col, then fused LSTM pointwise
        h16gemm<2><<<dim3(2048 / 64, Bz / 128), 256>>>(
            p_ctx16, p_wih16, W_ih, text, nullptr, nullptr, s);
    }

    // probs = out_h @ W_gen^T + b_gen : [B*S, C]
    h16gemm<3><<<dim3(2, (Bz * Sz) / 128), 256>>>(
        p_outh16, p_wgen16, nullptr, nullptr, b_gen, out, 0);
}